// round 1
// baseline (speedup 1.0000x reference)
#include <cuda_runtime.h>
#include <cuda_bf16.h>
#include <cstdint>

// Problem constants
#define B_  4
#define S_  8192
#define D_  1024
#define H_  16
#define DK_ 64
#define EPSF 1e-6f

// ---------------------------------------------------------------------------
// Scratch (device globals — no runtime allocation allowed)
// ---------------------------------------------------------------------------
__device__ float g_Q[(size_t)B_ * S_ * D_];   // relu(q@WqT)+eps
__device__ float g_K[(size_t)B_ * S_ * D_];   // relu(k@WkT)+eps
__device__ float g_V[(size_t)B_ * S_ * D_];   // v@WvT
__device__ float g_P[(size_t)B_ * S_ * D_];   // normalized qkv, pre-Wo
__device__ float g_kv[(size_t)B_ * H_ * DK_ * DK_];
__device__ float g_ktot[B_ * H_];

// ---------------------------------------------------------------------------
// GEMM: C[M,N] = A[M,K] @ W[N,K]^T   (both operands K-contiguous, row-major)
// act=1 -> relu(x)+eps epilogue
// ---------------------------------------------------------------------------
#define BM 128
#define BN 128
#define BK 16
#define TM 8
#define TN 8
#define APAD 4

__global__ __launch_bounds__(256) void gemm_xwT(
    const float* __restrict__ A, const float* __restrict__ W,
    float* __restrict__ C, int M, int N, int K, int act)
{
    __shared__ float As[BK][BM + APAD];
    __shared__ float Bs[BK][BN + APAD];

    const int tid = threadIdx.x;
    const int bx = blockIdx.x;   // N tile
    const int by = blockIdx.y;   // M tile
    const int tx = tid & 15;     // 16 col groups
    const int ty = tid >> 4;     // 16 row groups

    const float* Ablk = A + (size_t)by * BM * K;
    const float* Wblk = W + (size_t)bx * BN * K;

    float acc[TM][TN];
#pragma unroll
    for (int i = 0; i < TM; i++)
#pragma unroll
        for (int j = 0; j < TN; j++) acc[i][j] = 0.f;

    float regM[TM], regN[TN];

    for (int k0 = 0; k0 < K; k0 += BK) {
        // load 128x16 tiles of A and W, store transposed into smem
#pragma unroll
        for (int i = 0; i < 2; i++) {
            int f   = tid + i * 256;      // float4 index 0..511
            int row = f >> 2;             // 0..127
            int cv  = (f & 3) << 2;       // 0,4,8,12
            float4 av = *reinterpret_cast<const float4*>(Ablk + (size_t)row * K + k0 + cv);
            As[cv + 0][row] = av.x; As[cv + 1][row] = av.y;
            As[cv + 2][row] = av.z; As[cv + 3][row] = av.w;
            float4 wv = *reinterpret_cast<const float4*>(Wblk + (size_t)row * K + k0 + cv);
            Bs[cv + 0][row] = wv.x; Bs[cv + 1][row] = wv.y;
            Bs[cv + 2][row] = wv.z; Bs[cv + 3][row] = wv.w;
        }
        __syncthreads();

#pragma unroll
        for (int k = 0; k < BK; k++) {
#pragma unroll
            for (int i = 0; i < TM; i++) regM[i] = As[k][ty * TM + i];
#pragma unroll
            for (int j = 0; j < TN; j++) regN[j] = Bs[k][tx * TN + j];
#pragma unroll
            for (int i = 0; i < TM; i++)
#pragma unroll
                for (int j = 0; j < TN; j++)
                    acc[i][j] = fmaf(regM[i], regN[j], acc[i][j]);
        }
        __syncthreads();
    }

#pragma unroll
    for (int i = 0; i < TM; i++) {
        int row = by * BM + ty * TM + i;
#pragma unroll
        for (int j = 0; j < TN; j += 4) {
            int col = bx * BN + tx * TN + j;
            float4 v;
            v.x = acc[i][j + 0]; v.y = acc[i][j + 1];
            v.z = acc[i][j + 2]; v.w = acc[i][j + 3];
            if (act) {
                v.x = fmaxf(v.x, 0.f) + EPSF; v.y = fmaxf(v.y, 0.f) + EPSF;
                v.z = fmaxf(v.z, 0.f) + EPSF; v.w = fmaxf(v.w, 0.f) + EPSF;
            }
            *reinterpret_cast<float4*>(C + (size_t)row * N + col) = v;
        }
    }
}

// ---------------------------------------------------------------------------
// Zero kv / ktot (graph replays => must re-zero every launch)
// ---------------------------------------------------------------------------
__global__ void zero_kv()
{
    int i = blockIdx.x * blockDim.x + threadIdx.x;
    if (i < B_ * H_ * DK_ * DK_) g_kv[i] = 0.f;
    if (i < B_ * H_) g_ktot[i] = 0.f;
}

// ---------------------------------------------------------------------------
// kv[b,h,d,e] = sum_s K[b,s,h,d] * V[b,s,h,e]  ;  ktot[b,h] = sum_{s,d} K
// grid: (B*H, S/SCHUNK), 256 threads, atomic accumulation across chunks
// ---------------------------------------------------------------------------
#define SCHUNK 512
#define SSTAGE 8

__global__ __launch_bounds__(256) void kv_reduce(
    const float* __restrict__ Kb, const float* __restrict__ Vb)
{
    const int bh = blockIdx.x;
    const int b = bh >> 4, h = bh & 15;
    const int s0 = blockIdx.y * SCHUNK;

    __shared__ float sK[SSTAGE][DK_];
    __shared__ float sV[SSTAGE][DK_];
    __shared__ float red[256];

    const int tid = threadIdx.x;
    const int d0 = (tid >> 4) << 2;   // 0..60
    const int e0 = (tid & 15) << 2;   // 0..60

    float acc[4][4];
#pragma unroll
    for (int i = 0; i < 4; i++)
#pragma unroll
        for (int j = 0; j < 4; j++) acc[i][j] = 0.f;

    float ksum = 0.f;
    const size_t base = ((size_t)b * S_ + s0) * D_ + h * DK_;

    for (int so = 0; so < SCHUNK; so += SSTAGE) {
#pragma unroll
        for (int i = 0; i < 2; i++) {
            int idx = tid + i * 256;          // 0..511
            int sr = idx >> 6, dd = idx & 63;
            size_t off = base + (size_t)(so + sr) * D_ + dd;
            float kval = Kb[off];
            sK[sr][dd] = kval; ksum += kval;
            sV[sr][dd] = Vb[off];
        }
        __syncthreads();
#pragma unroll
        for (int sr = 0; sr < SSTAGE; sr++) {
            float kd[4], ve[4];
#pragma unroll
            for (int i = 0; i < 4; i++) { kd[i] = sK[sr][d0 + i]; ve[i] = sV[sr][e0 + i]; }
#pragma unroll
            for (int i = 0; i < 4; i++)
#pragma unroll
                for (int j = 0; j < 4; j++)
                    acc[i][j] = fmaf(kd[i], ve[j], acc[i][j]);
        }
        __syncthreads();
    }

    float* kvp = g_kv + (size_t)bh * DK_ * DK_;
#pragma unroll
    for (int i = 0; i < 4; i++)
#pragma unroll
        for (int j = 0; j < 4; j++)
            atomicAdd(&kvp[(d0 + i) * DK_ + e0 + j], acc[i][j]);

    red[tid] = ksum;
    __syncthreads();
    for (int off = 128; off > 0; off >>= 1) {
        if (tid < off) red[tid] += red[tid + off];
        __syncthreads();
    }
    if (tid == 0) atomicAdd(&g_ktot[bh], red[0]);
}

// ---------------------------------------------------------------------------
// P[b,s,h*64+e] = (sum_d Q[b,s,h,d]*kv[b,h,d,e]) / (rowsum(Q)*ktot[b,h] + eps)
// grid: (B*H, S/SC3), 256 threads = 4 groups of 64 (one s each per pass)
// ---------------------------------------------------------------------------
#define SC3 256

__global__ __launch_bounds__(256) void apply_kv(
    const float* __restrict__ Qb, float* __restrict__ P)
{
    const int bh = blockIdx.x;
    const int b = bh >> 4, h = bh & 15;

    __shared__ float skv[DK_ * DK_];
    __shared__ float sQ[4][DK_];

    for (int i = threadIdx.x; i < DK_ * DK_; i += 256)
        skv[i] = g_kv[(size_t)bh * DK_ * DK_ + i];
    __syncthreads();

    const float ktv = g_ktot[bh];
    const int grp = threadIdx.x >> 6;  // 0..3
    const int e   = threadIdx.x & 63;
    const int s0  = blockIdx.y * SC3;

    for (int si = 0; si < SC3; si += 4) {
        int s = s0 + si + grp;
        size_t off = ((size_t)b * S_ + s) * D_ + h * DK_;
        sQ[grp][e] = Qb[off + e];
        __syncthreads();
        float rsum = 0.f, acc = 0.f;
#pragma unroll
        for (int d = 0; d < DK_; d++) {
            float qd = sQ[grp][d];
            rsum += qd;
            acc = fmaf(qd, skv[d * DK_ + e], acc);
        }
        float nrm = 1.f / (rsum * ktv + EPSF);
        P[off + e] = acc * nrm;
        __syncthreads();
    }
}

// ---------------------------------------------------------------------------
// Launch
// ---------------------------------------------------------------------------
extern "C" void kernel_launch(void* const* d_in, const int* in_sizes, int n_in,
                              void* d_out, int out_size)
{
    const float* q  = (const float*)d_in[0];
    const float* k  = (const float*)d_in[1];
    const float* v  = (const float*)d_in[2];
    const float* Wq = (const float*)d_in[3];
    const float* Wk = (const float*)d_in[4];
    const float* Wv = (const float*)d_in[5];
    const float* Wo = (const float*)d_in[6];
    float* out = (float*)d_out;

    float *Qb, *Kb, *Vb, *Pb;
    cudaGetSymbolAddress((void**)&Qb, g_Q);
    cudaGetSymbolAddress((void**)&Kb, g_K);
    cudaGetSymbolAddress((void**)&Vb, g_V);
    cudaGetSymbolAddress((void**)&Pb, g_P);

    const int M = B_ * S_;
    dim3 gg(D_ / BN, M / BM);

    gemm_xwT<<<gg, 256>>>(q, Wq, Qb, M, D_, D_, 1);
    gemm_xwT<<<gg, 256>>>(k, Wk, Kb, M, D_, D_, 1);
    gemm_xwT<<<gg, 256>>>(v, Wv, Vb, M, D_, D_, 0);

    zero_kv<<<(B_ * H_ * DK_ * DK_ + 255) / 256, 256>>>();
    kv_reduce<<<dim3(B_ * H_, S_ / SCHUNK), 256>>>(Kb, Vb);
    apply_kv<<<dim3(B_ * H_, S_ / SC3), 256>>>(Qb, Pb);

    gemm_xwT<<<gg, 256>>>(Pb, Wo, out, M, D_, D_, 0);
}

// round 4
// speedup vs baseline: 2.4206x; 2.4206x over previous
#include <cuda_runtime.h>
#include <cuda_bf16.h>
#include <cstdint>

// Problem constants
#define B_  4
#define S_  8192
#define D_  1024
#define H_  16
#define DK_ 64
#define EPSF 1e-6f
#define MROWS (B_ * S_)

// ---------------------------------------------------------------------------
// Scratch (device globals — no runtime allocation allowed)
// ---------------------------------------------------------------------------
__device__ float g_Q[(size_t)B_ * S_ * D_];
__device__ float g_K[(size_t)B_ * S_ * D_];
__device__ float g_V[(size_t)B_ * S_ * D_];
__device__ float g_P[(size_t)B_ * S_ * D_];
__device__ float g_kv[(size_t)B_ * H_ * DK_ * DK_];
__device__ float g_ktot[B_ * H_];
__device__ __nv_bfloat16 g_Wh[4ull * 1024 * 1024];
__device__ __nv_bfloat16 g_Wl[4ull * 1024 * 1024];

// ---------------------------------------------------------------------------
// PTX helpers (sm_80-level PTX only — ptxas target is sm_103 non-'a')
// ---------------------------------------------------------------------------
__device__ __forceinline__ uint32_t smem_u32(const void* p) {
    uint32_t a;
    asm("{ .reg .u64 t; cvta.to.shared.u64 t, %1; cvt.u32.u64 %0, t; }"
        : "=r"(a) : "l"(p));
    return a;
}
__device__ __forceinline__ void ldsm_x4(uint32_t& r0, uint32_t& r1,
                                        uint32_t& r2, uint32_t& r3, uint32_t addr) {
    asm volatile("ldmatrix.sync.aligned.m8n8.x4.shared.b16 {%0,%1,%2,%3}, [%4];"
                 : "=r"(r0), "=r"(r1), "=r"(r2), "=r"(r3) : "r"(addr));
}
__device__ __forceinline__ void mma_bf16(float* c, const uint32_t* a, const uint32_t* b) {
    asm volatile(
        "mma.sync.aligned.m16n8k16.row.col.f32.bf16.bf16.f32 "
        "{%0,%1,%2,%3}, {%4,%5,%6,%7}, {%8,%9}, {%0,%1,%2,%3};"
        : "+f"(c[0]), "+f"(c[1]), "+f"(c[2]), "+f"(c[3])
        : "r"(a[0]), "r"(a[1]), "r"(a[2]), "r"(a[3]), "r"(b[0]), "r"(b[1]));
}
__device__ __forceinline__ void cpa16(uint32_t dst, const void* src) {
    asm volatile("cp.async.ca.shared.global [%0], [%1], 16;" :: "r"(dst), "l"(src));
}
__device__ __forceinline__ void cpa_commit() {
    asm volatile("cp.async.commit_group;" ::: "memory");
}
__device__ __forceinline__ void cpa_wait1() {
    asm volatile("cp.async.wait_group 1;" ::: "memory");
}
__device__ __forceinline__ void cpa_wait0() {
    asm volatile("cp.async.wait_group 0;" ::: "memory");
}
__device__ __forceinline__ void sts64(uint32_t addr, uint32_t a, uint32_t b) {
    asm volatile("st.shared.v2.b32 [%0], {%1, %2};"
                 :: "r"(addr), "r"(a), "r"(b) : "memory");
}
__device__ __forceinline__ uint32_t pack_hi(float x, float y) {
    unsigned short hx = __bfloat16_as_ushort(__float2bfloat16(x));
    unsigned short hy = __bfloat16_as_ushort(__float2bfloat16(y));
    return ((uint32_t)hy << 16) | hx;
}
__device__ __forceinline__ uint32_t pack_lo(float x, float y) {
    float rx = x - __bfloat162float(__float2bfloat16(x));
    float ry = y - __bfloat162float(__float2bfloat16(y));
    unsigned short lx = __bfloat16_as_ushort(__float2bfloat16(rx));
    unsigned short ly = __bfloat16_as_ushort(__float2bfloat16(ry));
    return ((uint32_t)ly << 16) | lx;
}

// ---------------------------------------------------------------------------
// Weight pre-split: W fp32 -> Wh + Wl bf16 (hi/lo decomposition)
// ---------------------------------------------------------------------------
__global__ __launch_bounds__(256) void split_w(
    const float* __restrict__ W, __nv_bfloat16* __restrict__ Wh,
    __nv_bfloat16* __restrict__ Wl)
{
    int i = (blockIdx.x * 256 + threadIdx.x) * 4;
    float4 v = *reinterpret_cast<const float4*>(W + i);
    uint32_t* whp = reinterpret_cast<uint32_t*>(Wh + i);
    uint32_t* wlp = reinterpret_cast<uint32_t*>(Wl + i);
    whp[0] = pack_hi(v.x, v.y);
    whp[1] = pack_hi(v.z, v.w);
    wlp[0] = pack_lo(v.x, v.y);
    wlp[1] = pack_lo(v.z, v.w);
}

// ---------------------------------------------------------------------------
// HMMA GEMM: C[M,1024] = A[M,1024] @ W[1024,1024]^T
// CTA tile 128x128, BK=32, 8 warps of 64x32, bf16 3-pass split.
// Smem rows padded to 40 elems (80B) -> conflict-free ldmatrix.
// ---------------------------------------------------------------------------
#define PADW   40
#define TILEB  (128 * PADW * 2)        // 10240 bytes per sub-tile
#define OFF_AH 0
#define OFF_AL (1 * TILEB)
#define OFF_WH (2 * TILEB)
#define OFF_WL (3 * TILEB)
#define STAGE  (4 * TILEB)             // 40960
#define SMEMSZ (2 * STAGE)             // 81920

__global__ __launch_bounds__(256, 2) void gemm_tc(
    const float* __restrict__ A,
    const __nv_bfloat16* __restrict__ Wh,
    const __nv_bfloat16* __restrict__ Wl,
    float* __restrict__ C, int act)
{
    extern __shared__ __align__(128) char smc[];
    const uint32_t sb0 = smem_u32(smc);
    const int tid = threadIdx.x;
    const int lane = tid & 31, w = tid >> 5;
    const int wm = w >> 2, wn = w & 3;
    const int bx = blockIdx.x, by = blockIdx.y;

    const float* Ab = A + (size_t)by * 128 * 1024;
    const __nv_bfloat16* WhB = Wh + (size_t)bx * 128 * 1024;
    const __nv_bfloat16* WlB = Wl + (size_t)bx * 128 * 1024;

    float acc[4][4][4];
#pragma unroll
    for (int i = 0; i < 4; i++)
#pragma unroll
        for (int j = 0; j < 4; j++)
#pragma unroll
            for (int q = 0; q < 4; q++) acc[i][j][q] = 0.f;

    float4 areg[4];
    uint32_t fa[4][4], fb[4][2];

    // ldmatrix per-lane byte offsets (within sub-tile base)
    const int aRow = lane & 15;
    const int aK   = (lane >> 4) << 3;
    const int bRow = ((lane >> 4) << 3) + (lane & 7);
    const int bK   = ((lane >> 3) & 1) << 3;
    const uint32_t aOff = (uint32_t)((wm * 64 + aRow) * PADW + aK) * 2;
    const uint32_t bOff = (uint32_t)((wn * 32 + bRow) * PADW + bK) * 2;

    auto LdgA = [&](int k0) {
#pragma unroll
        for (int i = 0; i < 4; i++) {
            int idx = tid + i * 256;
            areg[i] = *reinterpret_cast<const float4*>(
                Ab + (size_t)(idx >> 3) * 1024 + k0 + ((idx & 7) << 2));
        }
    };
    auto StsA = [&](uint32_t sb) {
#pragma unroll
        for (int i = 0; i < 4; i++) {
            int idx = tid + i * 256;
            int r = idx >> 3, cc = (idx & 7) << 2;
            uint32_t off = (uint32_t)(r * 80 + cc * 2);
            float4 v = areg[i];
            sts64(sb + OFF_AH + off, pack_hi(v.x, v.y), pack_hi(v.z, v.w));
            sts64(sb + OFF_AL + off, pack_lo(v.x, v.y), pack_lo(v.z, v.w));
        }
    };
    auto CpW = [&](uint32_t sb, int k0) {
#pragma unroll
        for (int i = 0; i < 2; i++) {
            int j = tid + i * 256;
            int r = j >> 2, s = j & 3;
            uint32_t off = (uint32_t)(r * 80 + s * 16);
            size_t goff = (size_t)r * 1024 + k0 + s * 8;
            cpa16(sb + OFF_WH + off, WhB + goff);
            cpa16(sb + OFF_WL + off, WlB + goff);
        }
    };
    auto LdAfrag = [&](uint32_t base) {
#pragma unroll
        for (int mt = 0; mt < 4; mt++)
            ldsm_x4(fa[mt][0], fa[mt][1], fa[mt][2], fa[mt][3],
                    base + (uint32_t)mt * 16 * 80);
    };
    auto LdBfrag = [&](uint32_t base) {
        ldsm_x4(fb[0][0], fb[0][1], fb[1][0], fb[1][1], base);
        ldsm_x4(fb[2][0], fb[2][1], fb[3][0], fb[3][1], base + 16 * 80);
    };
    auto MmaAll = [&]() {
#pragma unroll
        for (int mt = 0; mt < 4; mt++)
#pragma unroll
            for (int nf = 0; nf < 4; nf++)
                mma_bf16(acc[mt][nf], fa[mt], fb[nf]);
    };

    // Prologue: stage0 <- chunk0 (A STS + W cp.async), stage1 <- W chunk1
    LdgA(0);
    StsA(sb0);
    CpW(sb0, 0);
    cpa_commit();
    LdgA(32);
    CpW(sb0 + STAGE, 32);
    cpa_commit();

    for (int c = 0; c < 32; c++) {
        const uint32_t sb = sb0 + (uint32_t)(c & 1) * STAGE;
        if (c < 31) cpa_wait1(); else cpa_wait0();
        __syncthreads();

#pragma unroll
        for (int ks = 0; ks < 2; ks++) {
            const uint32_t ko = (uint32_t)ks * 32;   // 16 elems * 2B
            LdBfrag(sb + OFF_WH + bOff + ko);
            LdAfrag(sb + OFF_AH + aOff + ko);
            MmaAll();                    // Ah * Wh
            LdAfrag(sb + OFF_AL + aOff + ko);
            MmaAll();                    // Al * Wh
            LdBfrag(sb + OFF_WL + bOff + ko);
            LdAfrag(sb + OFF_AH + aOff + ko);
            MmaAll();                    // Ah * Wl
        }
        __syncthreads();

        if (c < 31) StsA(sb0 + (uint32_t)((c + 1) & 1) * STAGE);
        if (c < 30) {
            LdgA((c + 2) * 32);
            CpW(sb, (c + 2) * 32);
        }
        cpa_commit();
    }

    // Epilogue
    const int mBase = by * 128 + wm * 64 + (lane >> 2);
    const int nBase = bx * 128 + wn * 32 + (lane & 3) * 2;
#pragma unroll
    for (int mt = 0; mt < 4; mt++) {
#pragma unroll
        for (int nf = 0; nf < 4; nf++) {
            int m = mBase + mt * 16;
            int n = nBase + nf * 8;
            float2 v0 = make_float2(acc[mt][nf][0], acc[mt][nf][1]);
            float2 v1 = make_float2(acc[mt][nf][2], acc[mt][nf][3]);
            if (act) {
                v0.x = fmaxf(v0.x, 0.f) + EPSF; v0.y = fmaxf(v0.y, 0.f) + EPSF;
                v1.x = fmaxf(v1.x, 0.f) + EPSF; v1.y = fmaxf(v1.y, 0.f) + EPSF;
            }
            *reinterpret_cast<float2*>(C + (size_t)m * 1024 + n) = v0;
            *reinterpret_cast<float2*>(C + (size_t)(m + 8) * 1024 + n) = v1;
        }
    }
}

// ---------------------------------------------------------------------------
// Zero kv / ktot
// ---------------------------------------------------------------------------
__global__ void zero_kv()
{
    int i = blockIdx.x * blockDim.x + threadIdx.x;
    if (i < B_ * H_ * DK_ * DK_) g_kv[i] = 0.f;
    if (i < B_ * H_) g_ktot[i] = 0.f;
}

// ---------------------------------------------------------------------------
// kv[b,h,d,e] = sum_s K[b,s,h,d] * V[b,s,h,e] ; ktot[b,h] = sum K
// ---------------------------------------------------------------------------
#define SCHUNK 512
#define SSTAGE 8

__global__ __launch_bounds__(256) void kv_reduce(
    const float* __restrict__ Kb, const float* __restrict__ Vb)
{
    const int bh = blockIdx.x;
    const int b = bh >> 4, h = bh & 15;
    const int s0 = blockIdx.y * SCHUNK;

    __shared__ float sK[SSTAGE][DK_];
    __shared__ float sV[SSTAGE][DK_];
    __shared__ float red[256];

    const int tid = threadIdx.x;
    const int d0 = (tid >> 4) << 2;
    const int e0 = (tid & 15) << 2;

    float acc[4][4];
#pragma unroll
    for (int i = 0; i < 4; i++)
#pragma unroll
        for (int j = 0; j < 4; j++) acc[i][j] = 0.f;

    float ksum = 0.f;
    const size_t base = ((size_t)b * S_ + s0) * D_ + h * DK_;

    for (int so = 0; so < SCHUNK; so += SSTAGE) {
#pragma unroll
        for (int i = 0; i < 2; i++) {
            int idx = tid + i * 256;
            int sr = idx >> 6, dd = idx & 63;
            size_t off = base + (size_t)(so + sr) * D_ + dd;
            float kval = Kb[off];
            sK[sr][dd] = kval; ksum += kval;
            sV[sr][dd] = Vb[off];
        }
        __syncthreads();
#pragma unroll
        for (int sr = 0; sr < SSTAGE; sr++) {
            float kd[4], ve[4];
#pragma unroll
            for (int i = 0; i < 4; i++) { kd[i] = sK[sr][d0 + i]; ve[i] = sV[sr][e0 + i]; }
#pragma unroll
            for (int i = 0; i < 4; i++)
#pragma unroll
                for (int j = 0; j < 4; j++)
                    acc[i][j] = fmaf(kd[i], ve[j], acc[i][j]);
        }
        __syncthreads();
    }

    float* kvp = g_kv + (size_t)bh * DK_ * DK_;
#pragma unroll
    for (int i = 0; i < 4; i++)
#pragma unroll
        for (int j = 0; j < 4; j++)
            atomicAdd(&kvp[(d0 + i) * DK_ + e0 + j], acc[i][j]);

    red[tid] = ksum;
    __syncthreads();
    for (int off = 128; off > 0; off >>= 1) {
        if (tid < off) red[tid] += red[tid + off];
        __syncthreads();
    }
    if (tid == 0) atomicAdd(&g_ktot[bh], red[0]);
}

// ---------------------------------------------------------------------------
// P = (Q @ kv) / (rowsum(Q) * ktot + eps)
// ---------------------------------------------------------------------------
#define SC3 256

__global__ __launch_bounds__(256) void apply_kv(
    const float* __restrict__ Qb, float* __restrict__ P)
{
    const int bh = blockIdx.x;
    const int b = bh >> 4, h = bh & 15;

    __shared__ float skv[DK_ * DK_];
    __shared__ float sQ[4][DK_];

    for (int i = threadIdx.x; i < DK_ * DK_; i += 256)
        skv[i] = g_kv[(size_t)bh * DK_ * DK_ + i];
    __syncthreads();

    const float ktv = g_ktot[bh];
    const int grp = threadIdx.x >> 6;
    const int e   = threadIdx.x & 63;
    const int s0  = blockIdx.y * SC3;

    for (int si = 0; si < SC3; si += 4) {
        int s = s0 + si + grp;
        size_t off = ((size_t)b * S_ + s) * D_ + h * DK_;
        sQ[grp][e] = Qb[off + e];
        __syncthreads();
        float rsum = 0.f, acc = 0.f;
#pragma unroll
        for (int d = 0; d < DK_; d++) {
            float qd = sQ[grp][d];
            rsum += qd;
            acc = fmaf(qd, skv[d * DK_ + e], acc);
        }
        float nrm = 1.f / (rsum * ktv + EPSF);
        P[off + e] = acc * nrm;
        __syncthreads();
    }
}

// ---------------------------------------------------------------------------
// Launch
// ---------------------------------------------------------------------------
extern "C" void kernel_launch(void* const* d_in, const int* in_sizes, int n_in,
                              void* d_out, int out_size)
{
    const float* q  = (const float*)d_in[0];
    const float* k  = (const float*)d_in[1];
    const float* v  = (const float*)d_in[2];
    const float* Wq = (const float*)d_in[3];
    const float* Wk = (const float*)d_in[4];
    const float* Wv = (const float*)d_in[5];
    const float* Wo = (const float*)d_in[6];
    float* out = (float*)d_out;

    float *Qb, *Kb, *Vb, *Pb;
    __nv_bfloat16 *whp, *wlp;
    cudaGetSymbolAddress((void**)&Qb, g_Q);
    cudaGetSymbolAddress((void**)&Kb, g_K);
    cudaGetSymbolAddress((void**)&Vb, g_V);
    cudaGetSymbolAddress((void**)&Pb, g_P);
    cudaGetSymbolAddress((void**)&whp, g_Wh);
    cudaGetSymbolAddress((void**)&wlp, g_Wl);

    cudaFuncSetAttribute(gemm_tc, cudaFuncAttributeMaxDynamicSharedMemorySize,
                         SMEMSZ);

    const size_t WSTRIDE = 1024ull * 1024ull;

    // Pre-split weights to bf16 hi/lo
    split_w<<<1024, 256>>>(Wq, whp + 0 * WSTRIDE, wlp + 0 * WSTRIDE);
    split_w<<<1024, 256>>>(Wk, whp + 1 * WSTRIDE, wlp + 1 * WSTRIDE);
    split_w<<<1024, 256>>>(Wv, whp + 2 * WSTRIDE, wlp + 2 * WSTRIDE);
    split_w<<<1024, 256>>>(Wo, whp + 3 * WSTRIDE, wlp + 3 * WSTRIDE);

    dim3 gg(8, MROWS / 128);   // x = N tiles (fast), y = M tiles

    gemm_tc<<<gg, 256, SMEMSZ>>>(q, whp + 0 * WSTRIDE, wlp + 0 * WSTRIDE, Qb, 1);
    gemm_tc<<<gg, 256, SMEMSZ>>>(k, whp + 1 * WSTRIDE, wlp + 1 * WSTRIDE, Kb, 1);
    gemm_tc<<<gg, 256, SMEMSZ>>>(v, whp + 2 * WSTRIDE, wlp + 2 * WSTRIDE, Vb, 0);

    zero_kv<<<(B_ * H_ * DK_ * DK_ + 255) / 256, 256>>>();
    kv_reduce<<<dim3(B_ * H_, S_ / SCHUNK), 256>>>(Kb, Vb);
    apply_kv<<<dim3(B_ * H_, S_ / SC3), 256>>>(Qb, Pb);

    gemm_tc<<<gg, 256, SMEMSZ>>>(Pb, whp + 3 * WSTRIDE, wlp + 3 * WSTRIDE, out, 0);
}